// round 14
// baseline (speedup 1.0000x reference)
#include <cuda_runtime.h>
#include <cuda_bf16.h>
#include <cstdint>

// Problem dims (fixed)
#define B_   8
#define L_   2048
#define E_   1024
#define M_   (B_ * L_)   // 16384
#define RAD  5           // Gaussian truncation; dropped mass ~3e-6 rel (renormalized)
#define KP_  768         // packed width (heads 3,4 'first'/'last' removed)

// ---------------------------------------------------------------------------
// Scratch (__device__ globals; allocation-free rule)
// ---------------------------------------------------------------------------
__device__ __nv_bfloat16 g_Xh[(size_t)M_ * E_];
__device__ __nv_bfloat16 g_Xl[(size_t)M_ * E_];
__device__ __nv_bfloat16 g_Wih[(size_t)KP_ * E_];   // W_in rows packed [768,1024]
__device__ __nv_bfloat16 g_Wil[(size_t)KP_ * E_];
__device__ __nv_bfloat16 g_Wph[(size_t)E_ * KP_];   // W_out cols packed [1024,768]
__device__ __nv_bfloat16 g_Wpl[(size_t)E_ * KP_];
__device__ float         g_Vf [(size_t)M_ * KP_];   // packed V [M,768]
__device__ __nv_bfloat16 g_Uh[(size_t)M_ * KP_];    // packed U [M,768]
__device__ __nv_bfloat16 g_Ul[(size_t)M_ * KP_];
__device__ float         g_vbar[96 * 256];          // V rows for const heads (exact fp32)
__device__ float         g_ubar[B_ * 256];          // per-batch const-head values
__device__ float         g_yv[B_ * E_];             // per-batch broadcast output

__device__ __forceinline__ uint32_t smem_u32(const void* p) {
    uint32_t a;
    asm("{ .reg .u64 t; cvta.to.shared.u64 t, %1; cvt.u32.u64 %0, t; }" : "=r"(a) : "l"(p));
    return a;
}

#define CP_ASYNC16(dst, src) \
    asm volatile("cp.async.cg.shared.global [%0], [%1], 16;" :: "r"(dst), "l"(src))
#define CP_COMMIT() asm volatile("cp.async.commit_group;")
#define CP_WAIT(n)  asm volatile("cp.async.wait_group %0;" :: "n"(n))

#define LDSM_X4(r0, r1, r2, r3, addr)                                        \
    asm volatile("ldmatrix.sync.aligned.m8n8.x4.shared.b16 {%0,%1,%2,%3}, [%4];" \
                 : "=r"(r0), "=r"(r1), "=r"(r2), "=r"(r3) : "r"(addr))

#define MMA16816(acc, ar, b0, b1)                                            \
    asm volatile("mma.sync.aligned.m16n8k16.row.col.f32.bf16.bf16.f32 "      \
                 "{%0,%1,%2,%3}, {%4,%5,%6,%7}, {%8,%9}, {%0,%1,%2,%3};"     \
                 : "+f"((acc)[0]), "+f"((acc)[1]), "+f"((acc)[2]), "+f"((acc)[3]) \
                 : "r"((ar)[0]), "r"((ar)[1]), "r"((ar)[2]), "r"((ar)[3]),   \
                   "r"(b0), "r"(b1))

// ---------------------------------------------------------------------------
// GEMM: C[M, NOUT-grid] = A[M,KD] @ W[*,KD]^T via bf16 split (3 HMMA terms,
// shared fragments). BM=BN=128, BK=32, 256 threads, warp tile 32x64,
// 3-stage cp.async, 2 CTAs/SM. NOUT = row stride of C.
// ADDY: epilogue adds per-batch broadcast vector yv[b*1024+col].
// ---------------------------------------------------------------------------
#define GBM 128
#define GBN 128
#define GBK 32

#define T_AH 0
#define T_AL 8192
#define T_WH 16384
#define T_WL 24576
#define STG_BYTES 32768
#define SM_TOTAL (3 * STG_BYTES)   // 98304

template <int KD, int NOUT, bool ADDY>
__global__ __launch_bounds__(256, 2) void gemm_mma(
    const __nv_bfloat16* __restrict__ Ah, const __nv_bfloat16* __restrict__ Al,
    const __nv_bfloat16* __restrict__ Wh, const __nv_bfloat16* __restrict__ Wl,
    float* __restrict__ C, const float* __restrict__ yv)
{
    constexpr int NCHUNK = KD / GBK;
    extern __shared__ char smem[];
    const uint32_t smem_base = smem_u32(smem);

    const int tid  = threadIdx.x;
    const int wid  = tid >> 5;
    const int lane = tid & 31;
    const int wm   = wid & 3;    // M offset wm*32
    const int wn   = wid >> 2;   // N offset wn*64

    const size_t mrow0 = (size_t)blockIdx.y * GBM;
    const size_t nrow0 = (size_t)blockIdx.x * GBN;

    // --- cp.async per-thread addressing (tile: 128 rows x 4 x 16B) ---
    const int r0 = tid >> 2;
    const int r1 = r0 + 64;
    const int sg = tid & 3;
    const uint32_t so0 = (uint32_t)r0 * 64 + (uint32_t)((sg * 16) ^ (((r0 >> 1) & 3) << 4));
    const uint32_t so1 = (uint32_t)r1 * 64 + (uint32_t)((sg * 16) ^ (((r1 >> 1) & 3) << 4));
    const __nv_bfloat16* gAh0 = Ah + (mrow0 + r0) * KD + sg * 8;
    const __nv_bfloat16* gAh1 = Ah + (mrow0 + r1) * KD + sg * 8;
    const __nv_bfloat16* gAl0 = Al + (mrow0 + r0) * KD + sg * 8;
    const __nv_bfloat16* gAl1 = Al + (mrow0 + r1) * KD + sg * 8;
    const __nv_bfloat16* gWh0 = Wh + (nrow0 + r0) * KD + sg * 8;
    const __nv_bfloat16* gWh1 = Wh + (nrow0 + r1) * KD + sg * 8;
    const __nv_bfloat16* gWl0 = Wl + (nrow0 + r0) * KD + sg * 8;
    const __nv_bfloat16* gWl1 = Wl + (nrow0 + r1) * KD + sg * 8;

    // --- ldmatrix lane addressing (64B rows) ---
    uint32_t aBase[2], aSwz[2];
#pragma unroll
    for (int mt = 0; mt < 2; mt++) {
        const int r = wm * 32 + mt * 16 + (lane & 15);
        aBase[mt] = (uint32_t)r * 64;
        aSwz[mt]  = (uint32_t)(((r >> 1) & 3) << 4);
    }
    const uint32_t cselA = (uint32_t)(((lane >> 4) & 1) * 16);
    uint32_t bBase[4], bSwz[4];
#pragma unroll
    for (int g = 0; g < 4; g++) {
        const int r = wn * 64 + g * 16 + (lane & 7) + ((lane >> 4) & 1) * 8;
        bBase[g] = (uint32_t)r * 64;
        bSwz[g]  = (uint32_t)(((r >> 1) & 3) << 4);
    }
    const uint32_t cselB = (uint32_t)(((lane >> 3) & 1) * 16);

    float acc[2][8][4];
#pragma unroll
    for (int mt = 0; mt < 2; mt++)
#pragma unroll
        for (int nt = 0; nt < 8; nt++)
#pragma unroll
            for (int r = 0; r < 4; r++) acc[mt][nt][r] = 0.0f;

    auto load_chunk = [&](int ch, int stg) {
        const uint32_t sb = smem_base + (uint32_t)stg * STG_BYTES;
        const int kb = ch * GBK;
        CP_ASYNC16(sb + T_AH + so0, gAh0 + kb);
        CP_ASYNC16(sb + T_AH + so1, gAh1 + kb);
        CP_ASYNC16(sb + T_AL + so0, gAl0 + kb);
        CP_ASYNC16(sb + T_AL + so1, gAl1 + kb);
        CP_ASYNC16(sb + T_WH + so0, gWh0 + kb);
        CP_ASYNC16(sb + T_WH + so1, gWh1 + kb);
        CP_ASYNC16(sb + T_WL + so0, gWl0 + kb);
        CP_ASYNC16(sb + T_WL + so1, gWl1 + kb);
        CP_COMMIT();
    };

    load_chunk(0, 0);
    load_chunk(1, 1);

#pragma unroll 1
    for (int ch = 0; ch < NCHUNK; ch++) {
        if (ch + 1 < NCHUNK) { CP_WAIT(1); } else { CP_WAIT(0); }
        __syncthreads();
        if (ch + 2 < NCHUNK) load_chunk(ch + 2, (ch + 2) % 3);

        const uint32_t sb = smem_base + (uint32_t)(ch % 3) * STG_BYTES;
#pragma unroll
        for (int ks = 0; ks < 2; ks++) {
            const uint32_t kb = (uint32_t)(ks * 32);
            uint32_t ah[2][4], al[2][4];
#pragma unroll
            for (int mt = 0; mt < 2; mt++) {
                const uint32_t off = aBase[mt] + ((kb + cselA) ^ aSwz[mt]);
                LDSM_X4(ah[mt][0], ah[mt][1], ah[mt][2], ah[mt][3], sb + T_AH + off);
                LDSM_X4(al[mt][0], al[mt][1], al[mt][2], al[mt][3], sb + T_AL + off);
            }
#pragma unroll
            for (int g = 0; g < 4; g++) {
                const uint32_t boff = bBase[g] + ((kb + cselB) ^ bSwz[g]);
                uint32_t bh0, bh1, bh2, bh3, bl0, bl1, bl2, bl3;
                LDSM_X4(bh0, bh1, bh2, bh3, sb + T_WH + boff);
                LDSM_X4(bl0, bl1, bl2, bl3, sb + T_WL + boff);
#pragma unroll
                for (int mt = 0; mt < 2; mt++) {
                    MMA16816(acc[mt][g * 2],     ah[mt], bh0, bh1);
                    MMA16816(acc[mt][g * 2 + 1], ah[mt], bh2, bh3);
                    MMA16816(acc[mt][g * 2],     ah[mt], bl0, bl1);
                    MMA16816(acc[mt][g * 2 + 1], ah[mt], bl2, bl3);
                    MMA16816(acc[mt][g * 2],     al[mt], bh0, bh1);
                    MMA16816(acc[mt][g * 2 + 1], al[mt], bh2, bh3);
                }
            }
        }
    }

    // Epilogue (C stride = NOUT)
    const int qr = lane >> 2;
    const int qc = (lane & 3) * 2;
#pragma unroll
    for (int mt = 0; mt < 2; mt++) {
        const size_t r0e = mrow0 + wm * 32 + mt * 16 + qr;
        const int bb = (int)(r0e >> 11);
#pragma unroll
        for (int nt = 0; nt < 8; nt++) {
            const size_t col = nrow0 + wn * 64 + nt * 8 + qc;
            float a0 = acc[mt][nt][0], a1 = acc[mt][nt][1];
            float a2 = acc[mt][nt][2], a3 = acc[mt][nt][3];
            if (ADDY) {
                const float y0 = __ldg(yv + (size_t)bb * E_ + col);
                const float y1 = __ldg(yv + (size_t)bb * E_ + col + 1);
                a0 += y0; a1 += y1; a2 += y0; a3 += y1;
            }
            *(float2*)(C + r0e * NOUT + col)       = make_float2(a0, a1);
            *(float2*)(C + (r0e + 8) * NOUT + col) = make_float2(a2, a3);
        }
    }
}

// ---------------------------------------------------------------------------
// fp32 -> bf16 hi/lo split conversion (full width)
// ---------------------------------------------------------------------------
__global__ __launch_bounds__(256) void conv_split(
    const float* __restrict__ in, __nv_bfloat16* __restrict__ hi,
    __nv_bfloat16* __restrict__ lo, int n4)
{
    int idx = blockIdx.x * 256 + threadIdx.x;
    if (idx >= n4) return;
    float4 v = ((const float4*)in)[idx];
    __nv_bfloat16 h0 = __float2bfloat16(v.x), h1 = __float2bfloat16(v.y);
    __nv_bfloat16 h2 = __float2bfloat16(v.z), h3 = __float2bfloat16(v.w);
    __nv_bfloat16 l0 = __float2bfloat16(v.x - __bfloat162float(h0));
    __nv_bfloat16 l1 = __float2bfloat16(v.y - __bfloat162float(h1));
    __nv_bfloat16 l2 = __float2bfloat16(v.z - __bfloat162float(h2));
    __nv_bfloat16 l3 = __float2bfloat16(v.w - __bfloat162float(h3));
    __nv_bfloat162 hp0; hp0.x = h0; hp0.y = h1;
    __nv_bfloat162 hp1; hp1.x = h2; hp1.y = h3;
    __nv_bfloat162 lp0; lp0.x = l0; lp0.y = l1;
    __nv_bfloat162 lp1; lp1.x = l2; lp1.y = l3;
    uint2 hw, lw;
    hw.x = *(uint32_t*)&hp0; hw.y = *(uint32_t*)&hp1;
    lw.x = *(uint32_t*)&lp0; lw.y = *(uint32_t*)&lp1;
    ((uint2*)hi)[idx] = hw;
    ((uint2*)lo)[idx] = lw;
}

// ---------------------------------------------------------------------------
// W_in row-packed split: rows {0:384, 640:1024} -> [768, 1024]
// ---------------------------------------------------------------------------
__global__ __launch_bounds__(256) void conv_split_pack_rows(
    const float* __restrict__ in, __nv_bfloat16* __restrict__ hi,
    __nv_bfloat16* __restrict__ lo)
{
    int idx = blockIdx.x * 256 + threadIdx.x;   // over KP_*E_/4
    if (idx >= KP_ * E_ / 4) return;
    const int pos = idx * 4;
    const int np  = pos / E_;
    const int k   = pos % E_;
    const int n   = np < 384 ? np : np + 256;
    float4 v = *(const float4*)(in + (size_t)n * E_ + k);
    __nv_bfloat16 h0 = __float2bfloat16(v.x), h1 = __float2bfloat16(v.y);
    __nv_bfloat16 h2 = __float2bfloat16(v.z), h3 = __float2bfloat16(v.w);
    __nv_bfloat16 l0 = __float2bfloat16(v.x - __bfloat162float(h0));
    __nv_bfloat16 l1 = __float2bfloat16(v.y - __bfloat162float(h1));
    __nv_bfloat16 l2 = __float2bfloat16(v.z - __bfloat162float(h2));
    __nv_bfloat16 l3 = __float2bfloat16(v.w - __bfloat162float(h3));
    __nv_bfloat162 hp0; hp0.x = h0; hp0.y = h1;
    __nv_bfloat162 hp1; hp1.x = h2; hp1.y = h3;
    __nv_bfloat162 lp0; lp0.x = l0; lp0.y = l1;
    __nv_bfloat162 lp1; lp1.x = l2; lp1.y = l3;
    uint2 hw, lw;
    hw.x = *(uint32_t*)&hp0; hw.y = *(uint32_t*)&hp1;
    lw.x = *(uint32_t*)&lp0; lw.y = *(uint32_t*)&lp1;
    ((uint2*)hi)[idx] = hw;
    ((uint2*)lo)[idx] = lw;
}

// ---------------------------------------------------------------------------
// W_out col-packed split: cols {0:384, 640:1024} -> [1024, 768]
// ---------------------------------------------------------------------------
__global__ __launch_bounds__(256) void conv_split_pack(
    const float* __restrict__ in, __nv_bfloat16* __restrict__ hi,
    __nv_bfloat16* __restrict__ lo)
{
    int idx = blockIdx.x * 256 + threadIdx.x;   // over E_*KP_/4
    if (idx >= E_ * KP_ / 4) return;
    const int pos = idx * 4;
    const int n   = pos / KP_;
    const int kp  = pos % KP_;
    const int k   = kp < 384 ? kp : kp + 256;
    float4 v = *(const float4*)(in + (size_t)n * E_ + k);
    __nv_bfloat16 h0 = __float2bfloat16(v.x), h1 = __float2bfloat16(v.y);
    __nv_bfloat16 h2 = __float2bfloat16(v.z), h3 = __float2bfloat16(v.w);
    __nv_bfloat16 l0 = __float2bfloat16(v.x - __bfloat162float(h0));
    __nv_bfloat16 l1 = __float2bfloat16(v.y - __bfloat162float(h1));
    __nv_bfloat16 l2 = __float2bfloat16(v.z - __bfloat162float(h2));
    __nv_bfloat16 l3 = __float2bfloat16(v.w - __bfloat162float(h3));
    __nv_bfloat162 hp0; hp0.x = h0; hp0.y = h1;
    __nv_bfloat162 hp1; hp1.x = h2; hp1.y = h3;
    __nv_bfloat162 lp0; lp0.x = l0; lp0.y = l1;
    __nv_bfloat162 lp1; lp1.x = l2; lp1.y = l3;
    uint2 hw, lw;
    hw.x = *(uint32_t*)&hp0; hw.y = *(uint32_t*)&hp1;
    lw.x = *(uint32_t*)&lp0; lw.y = *(uint32_t*)&lp1;
    ((uint2*)hi)[idx] = hw;
    ((uint2*)lo)[idx] = lw;
}

__device__ __constant__ float c_wt[RAD + 1] = {
    1.0f, 0.60653066f, 0.13533528f, 0.011108997f, 3.3546263e-4f, 3.7266532e-6f};

// ---------------------------------------------------------------------------
// Gaussian smoothing on packed V [M,768] -> packed bf16 U [M,768].
// ---------------------------------------------------------------------------
__global__ __launch_bounds__(192) void smooth_pack(
    const float* __restrict__ V, __nv_bfloat16* __restrict__ Uh,
    __nv_bfloat16* __restrict__ Ul)
{
    const int n = blockIdx.x;        // b*L + q
    const int b = n >> 11;
    const int q = n & (L_ - 1);
    const int kp = threadIdx.x * 4;  // packed col
    const int hp = kp >> 7;          // 0..5

    int c;
    switch (hp % 3) {
        case 0:  c = q;     break;   // center
        case 1:  c = q - 1; break;   // left
        default: c = q + 1; break;   // right
    }

    float ax = 0.f, ay = 0.f, az = 0.f, aw = 0.f, wsum = 0.f;
#pragma unroll
    for (int d = -RAD; d <= RAD; d++) {
        const int j = c + d;
        if (j >= 0 && j < L_) {
            const float w = c_wt[d < 0 ? -d : d];
            wsum += w;
            const float4 v = *(const float4*)(V + ((size_t)b * L_ + j) * KP_ + kp);
            ax = fmaf(w, v.x, ax); ay = fmaf(w, v.y, ay);
            az = fmaf(w, v.z, az); aw = fmaf(w, v.w, aw);
        }
    }
    const float inv = 1.0f / wsum;
    ax *= inv; ay *= inv; az *= inv; aw *= inv;

    __nv_bfloat16 h0 = __float2bfloat16(ax), h1 = __float2bfloat16(ay);
    __nv_bfloat16 h2 = __float2bfloat16(az), h3 = __float2bfloat16(aw);
    __nv_bfloat16 l0 = __float2bfloat16(ax - __bfloat162float(h0));
    __nv_bfloat16 l1 = __float2bfloat16(ay - __bfloat162float(h1));
    __nv_bfloat16 l2 = __float2bfloat16(az - __bfloat162float(h2));
    __nv_bfloat16 l3 = __float2bfloat16(aw - __bfloat162float(h3));
    __nv_bfloat162 hp0; hp0.x = h0; hp0.y = h1;
    __nv_bfloat162 hp1; hp1.x = h2; hp1.y = h3;
    __nv_bfloat162 lp0; lp0.x = l0; lp0.y = l1;
    __nv_bfloat162 lp1; lp1.x = l2; lp1.y = l3;
    uint2 hw, lw;
    hw.x = *(uint32_t*)&hp0; hw.y = *(uint32_t*)&hp1;
    lw.x = *(uint32_t*)&lp0; lw.y = *(uint32_t*)&lp1;
    const size_t o = ((size_t)n * KP_ + kp) >> 2;
    ((uint2*)Uh)[o] = hw;
    ((uint2*)Ul)[o] = lw;
}

// ---------------------------------------------------------------------------
// vbar[v][p] = X[b, j(v), :] . W_in[384+p, :]   (exact fp32)
// v = b*12 + jj; jj<6 -> row jj; jj>=6 -> row L-12+jj (i.e. L-6..L-1).
// ---------------------------------------------------------------------------
__global__ __launch_bounds__(256) void vbar_kernel(
    const float* __restrict__ x, const float* __restrict__ W_in,
    float* __restrict__ vbar)
{
    __shared__ float xs[E_];
    const int v  = blockIdx.x;       // 0..95
    const int b  = v / 12;
    const int jj = v % 12;
    const int j  = jj < 6 ? jj : L_ - 12 + jj;
    const float* xr = x + ((size_t)b * L_ + j) * E_;
    for (int k = threadIdx.x; k < E_; k += 256) xs[k] = xr[k];
    __syncthreads();
    const float* wr = W_in + (size_t)(384 + threadIdx.x) * E_;
    float acc = 0.f;
#pragma unroll 8
    for (int k = 0; k < E_; k++) acc = fmaf(xs[k], wr[k], acc);
    vbar[v * 256 + threadIdx.x] = acc;
}

// ---------------------------------------------------------------------------
// ubar[b][p]: renormalized Gaussian over the 6 edge rows (exact fp32).
// ---------------------------------------------------------------------------
__global__ void ubar_kernel(const float* __restrict__ vbar, float* __restrict__ ubar)
{
    const int b = blockIdx.x;
    const int p = threadIdx.x;      // 0..255
    float acc = 0.f, wsum = 0.f;
    if (p < 128) {                  // 'first': center 0, rows j=0..5 (jj=j)
#pragma unroll
        for (int j = 0; j <= RAD; j++) {
            const float w = c_wt[j];
            wsum += w;
            acc = fmaf(w, vbar[(b * 12 + j) * 256 + p], acc);
        }
    } else {                        // 'last': center L-1, row L-1-d = jj 6+(5-d)
#pragma unroll
        for (int d = 0; d <= RAD; d++) {
            const float w = c_wt[d];
            wsum += w;
            acc = fmaf(w, vbar[(b * 12 + 6 + (RAD - d)) * 256 + p], acc);
        }
    }
    ubar[b * 256 + p] = acc / wsum;
}

// ---------------------------------------------------------------------------
// y[b][n] = sum_p ubar[b][p] * W_out[n][384+p]   (fp32, exact)
// ---------------------------------------------------------------------------
__global__ __launch_bounds__(256) void yvec_kernel(
    const float* __restrict__ ubar, const float* __restrict__ Wout,
    float* __restrict__ yv)
{
    __shared__ float us[256];
    const int b = blockIdx.x >> 2;
    const int n = (blockIdx.x & 3) * 256 + threadIdx.x;
    us[threadIdx.x] = ubar[b * 256 + threadIdx.x];
    __syncthreads();
    float acc = 0.f;
    const float* wr = Wout + (size_t)n * E_ + 384;
#pragma unroll 8
    for (int p = 0; p < 256; p++) acc = fmaf(us[p], wr[p], acc);
    yv[b * E_ + n] = acc;
}

// ---------------------------------------------------------------------------
extern "C" void kernel_launch(void* const* d_in, const int* in_sizes, int n_in,
                              void* d_out, int out_size)
{
    (void)in_sizes; (void)n_in; (void)out_size;
    const float* x     = (const float*)d_in[0];
    const float* W_in  = (const float*)d_in[1];
    const float* W_out = (const float*)d_in[2];
    float* out = (float*)d_out;

    __nv_bfloat16 *Xh, *Xl, *Wih, *Wil, *Wph, *Wpl, *Uh, *Ul;
    float *Vf, *vbar, *ubar, *yv;
    cudaGetSymbolAddress((void**)&Xh, g_Xh);
    cudaGetSymbolAddress((void**)&Xl, g_Xl);
    cudaGetSymbolAddress((void**)&Wih, g_Wih);
    cudaGetSymbolAddress((void**)&Wil, g_Wil);
    cudaGetSymbolAddress((void**)&Wph, g_Wph);
    cudaGetSymbolAddress((void**)&Wpl, g_Wpl);
    cudaGetSymbolAddress((void**)&Vf, g_Vf);
    cudaGetSymbolAddress((void**)&Uh, g_Uh);
    cudaGetSymbolAddress((void**)&Ul, g_Ul);
    cudaGetSymbolAddress((void**)&vbar, g_vbar);
    cudaGetSymbolAddress((void**)&ubar, g_ubar);
    cudaGetSymbolAddress((void**)&yv, g_yv);

    cudaFuncSetAttribute((const void*)gemm_mma<E_, KP_, false>,
                         cudaFuncAttributeMaxDynamicSharedMemorySize, SM_TOTAL);
    cudaFuncSetAttribute((const void*)gemm_mma<KP_, E_, true>,
                         cudaFuncAttributeMaxDynamicSharedMemorySize, SM_TOTAL);

    // Split conversions
    conv_split<<<(M_ * E_ / 4 + 255) / 256, 256>>>(x, Xh, Xl, M_ * E_ / 4);
    conv_split_pack_rows<<<(KP_ * E_ / 4 + 255) / 256, 256>>>(W_in, Wih, Wil);
    conv_split_pack<<<(E_ * KP_ / 4 + 255) / 256, 256>>>(W_out, Wph, Wpl);

    // Vp = X @ W_in_packed^T  (fp32, [M,768])
    dim3 grid1(KP_ / GBN, M_ / GBM);   // (6, 128)
    gemm_mma<E_, KP_, false><<<grid1, 256, SM_TOTAL>>>(Xh, Xl, Wih, Wil, Vf, nullptr);

    // const-head path (exact fp32 from raw inputs)
    vbar_kernel<<<96, 256>>>(x, W_in, vbar);
    ubar_kernel<<<B_, 256>>>(vbar, ubar);
    yvec_kernel<<<B_ * 4, 256>>>(ubar, W_out, yv);

    // U (packed) = gaussian smooth of Vp
    smooth_pack<<<M_, 192>>>(Vf, Uh, Ul);

    // out = U_packed @ W_out_packed^T + broadcast(yv)
    dim3 grid2(E_ / GBN, M_ / GBM);    // (8, 128)
    gemm_mma<KP_, E_, true><<<grid2, 256, SM_TOTAL>>>(Uh, Ul, Wph, Wpl, out, yv);
}

// round 15
// speedup vs baseline: 1.3506x; 1.3506x over previous
#include <cuda_runtime.h>
#include <cuda_bf16.h>
#include <cstdint>

// Problem dims (fixed)
#define B_   8
#define L_   2048
#define E_   1024
#define M_   (B_ * L_)   // 16384
#define RAD  5           // Gaussian truncation; dropped mass ~3e-6 rel (renormalized)
#define KP_  768         // packed width (heads 3,4 'first'/'last' removed)

// ---------------------------------------------------------------------------
// Scratch (__device__ globals; allocation-free rule)
// ---------------------------------------------------------------------------
__device__ __nv_bfloat16 g_Xh[(size_t)M_ * E_];
__device__ __nv_bfloat16 g_Xl[(size_t)M_ * E_];
__device__ __nv_bfloat16 g_Wih[(size_t)KP_ * E_];   // W_in rows packed [768,1024]
__device__ __nv_bfloat16 g_Wil[(size_t)KP_ * E_];
__device__ __nv_bfloat16 g_Wph[(size_t)E_ * KP_];   // W_out cols packed [1024,768]
__device__ __nv_bfloat16 g_Wpl[(size_t)E_ * KP_];
__device__ float         g_Vf [(size_t)M_ * KP_];   // packed V [M,768]
__device__ __nv_bfloat16 g_Uh[(size_t)M_ * KP_];    // packed U [M,768]
__device__ __nv_bfloat16 g_Ul[(size_t)M_ * KP_];
__device__ float         g_xbar[16 * E_];           // weighted x rows (b,h)
__device__ float         g_ubar[B_ * 256];          // per-batch const-head values
__device__ float         g_yv[B_ * E_];             // per-batch broadcast output

__device__ __forceinline__ uint32_t smem_u32(const void* p) {
    uint32_t a;
    asm("{ .reg .u64 t; cvta.to.shared.u64 t, %1; cvt.u32.u64 %0, t; }" : "=r"(a) : "l"(p));
    return a;
}

#define CP_ASYNC16(dst, src) \
    asm volatile("cp.async.cg.shared.global [%0], [%1], 16;" :: "r"(dst), "l"(src))
#define CP_COMMIT() asm volatile("cp.async.commit_group;")
#define CP_WAIT(n)  asm volatile("cp.async.wait_group %0;" :: "n"(n))

#define LDSM_X4(r0, r1, r2, r3, addr)                                        \
    asm volatile("ldmatrix.sync.aligned.m8n8.x4.shared.b16 {%0,%1,%2,%3}, [%4];" \
                 : "=r"(r0), "=r"(r1), "=r"(r2), "=r"(r3) : "r"(addr))

#define MMA16816(acc, ar, b0, b1)                                            \
    asm volatile("mma.sync.aligned.m16n8k16.row.col.f32.bf16.bf16.f32 "      \
                 "{%0,%1,%2,%3}, {%4,%5,%6,%7}, {%8,%9}, {%0,%1,%2,%3};"     \
                 : "+f"((acc)[0]), "+f"((acc)[1]), "+f"((acc)[2]), "+f"((acc)[3]) \
                 : "r"((ar)[0]), "r"((ar)[1]), "r"((ar)[2]), "r"((ar)[3]),   \
                   "r"(b0), "r"(b1))

// ---------------------------------------------------------------------------
// GEMM: C[M, grid-N] = A[M,KD] @ W[*,KD]^T via bf16 split (3 HMMA terms,
// shared fragments). BM=BN=128, BK=32, 256 threads, warp tile 32x64,
// 3-stage cp.async, 2 CTAs/SM. NOUT = row stride of C.
// ADDY: epilogue adds per-batch broadcast vector yv[b*1024+col].
// ---------------------------------------------------------------------------
#define GBM 128
#define GBN 128
#define GBK 32

#define T_AH 0
#define T_AL 8192
#define T_WH 16384
#define T_WL 24576
#define STG_BYTES 32768
#define SM_TOTAL (3 * STG_BYTES)   // 98304

template <int KD, int NOUT, bool ADDY>
__global__ __launch_bounds__(256, 2) void gemm_mma(
    const __nv_bfloat16* __restrict__ Ah, const __nv_bfloat16* __restrict__ Al,
    const __nv_bfloat16* __restrict__ Wh, const __nv_bfloat16* __restrict__ Wl,
    float* __restrict__ C, const float* __restrict__ yv)
{
    constexpr int NCHUNK = KD / GBK;
    extern __shared__ char smem[];
    const uint32_t smem_base = smem_u32(smem);

    const int tid  = threadIdx.x;
    const int wid  = tid >> 5;
    const int lane = tid & 31;
    const int wm   = wid & 3;    // M offset wm*32
    const int wn   = wid >> 2;   // N offset wn*64

    const size_t mrow0 = (size_t)blockIdx.y * GBM;
    const size_t nrow0 = (size_t)blockIdx.x * GBN;

    // --- cp.async per-thread addressing (tile: 128 rows x 4 x 16B) ---
    const int r0 = tid >> 2;
    const int r1 = r0 + 64;
    const int sg = tid & 3;
    const uint32_t so0 = (uint32_t)r0 * 64 + (uint32_t)((sg * 16) ^ (((r0 >> 1) & 3) << 4));
    const uint32_t so1 = (uint32_t)r1 * 64 + (uint32_t)((sg * 16) ^ (((r1 >> 1) & 3) << 4));
    const __nv_bfloat16* gAh0 = Ah + (mrow0 + r0) * KD + sg * 8;
    const __nv_bfloat16* gAh1 = Ah + (mrow0 + r1) * KD + sg * 8;
    const __nv_bfloat16* gAl0 = Al + (mrow0 + r0) * KD + sg * 8;
    const __nv_bfloat16* gAl1 = Al + (mrow0 + r1) * KD + sg * 8;
    const __nv_bfloat16* gWh0 = Wh + (nrow0 + r0) * KD + sg * 8;
    const __nv_bfloat16* gWh1 = Wh + (nrow0 + r1) * KD + sg * 8;
    const __nv_bfloat16* gWl0 = Wl + (nrow0 + r0) * KD + sg * 8;
    const __nv_bfloat16* gWl1 = Wl + (nrow0 + r1) * KD + sg * 8;

    // --- ldmatrix lane addressing (64B rows) ---
    uint32_t aBase[2], aSwz[2];
#pragma unroll
    for (int mt = 0; mt < 2; mt++) {
        const int r = wm * 32 + mt * 16 + (lane & 15);
        aBase[mt] = (uint32_t)r * 64;
        aSwz[mt]  = (uint32_t)(((r >> 1) & 3) << 4);
    }
    const uint32_t cselA = (uint32_t)(((lane >> 4) & 1) * 16);
    uint32_t bBase[4], bSwz[4];
#pragma unroll
    for (int g = 0; g < 4; g++) {
        const int r = wn * 64 + g * 16 + (lane & 7) + ((lane >> 4) & 1) * 8;
        bBase[g] = (uint32_t)r * 64;
        bSwz[g]  = (uint32_t)(((r >> 1) & 3) << 4);
    }
    const uint32_t cselB = (uint32_t)(((lane >> 3) & 1) * 16);

    float acc[2][8][4];
#pragma unroll
    for (int mt = 0; mt < 2; mt++)
#pragma unroll
        for (int nt = 0; nt < 8; nt++)
#pragma unroll
            for (int r = 0; r < 4; r++) acc[mt][nt][r] = 0.0f;

    auto load_chunk = [&](int ch, int stg) {
        const uint32_t sb = smem_base + (uint32_t)stg * STG_BYTES;
        const int kb = ch * GBK;
        CP_ASYNC16(sb + T_AH + so0, gAh0 + kb);
        CP_ASYNC16(sb + T_AH + so1, gAh1 + kb);
        CP_ASYNC16(sb + T_AL + so0, gAl0 + kb);
        CP_ASYNC16(sb + T_AL + so1, gAl1 + kb);
        CP_ASYNC16(sb + T_WH + so0, gWh0 + kb);
        CP_ASYNC16(sb + T_WH + so1, gWh1 + kb);
        CP_ASYNC16(sb + T_WL + so0, gWl0 + kb);
        CP_ASYNC16(sb + T_WL + so1, gWl1 + kb);
        CP_COMMIT();
    };

    load_chunk(0, 0);
    load_chunk(1, 1);

#pragma unroll 1
    for (int ch = 0; ch < NCHUNK; ch++) {
        if (ch + 1 < NCHUNK) { CP_WAIT(1); } else { CP_WAIT(0); }
        __syncthreads();
        if (ch + 2 < NCHUNK) load_chunk(ch + 2, (ch + 2) % 3);

        const uint32_t sb = smem_base + (uint32_t)(ch % 3) * STG_BYTES;
#pragma unroll
        for (int ks = 0; ks < 2; ks++) {
            const uint32_t kb = (uint32_t)(ks * 32);
            uint32_t ah[2][4], al[2][4];
#pragma unroll
            for (int mt = 0; mt < 2; mt++) {
                const uint32_t off = aBase[mt] + ((kb + cselA) ^ aSwz[mt]);
                LDSM_X4(ah[mt][0], ah[mt][1], ah[mt][2], ah[mt][3], sb + T_AH + off);
                LDSM_X4(al[mt][0], al[mt][1], al[mt][2], al[mt][3], sb + T_AL + off);
            }
#pragma unroll
            for (int g = 0; g < 4; g++) {
                const uint32_t boff = bBase[g] + ((kb + cselB) ^ bSwz[g]);
                uint32_t bh0, bh1, bh2, bh3, bl0, bl1, bl2, bl3;
                LDSM_X4(bh0, bh1, bh2, bh3, sb + T_WH + boff);
                LDSM_X4(bl0, bl1, bl2, bl3, sb + T_WL + boff);
#pragma unroll
                for (int mt = 0; mt < 2; mt++) {
                    MMA16816(acc[mt][g * 2],     ah[mt], bh0, bh1);
                    MMA16816(acc[mt][g * 2 + 1], ah[mt], bh2, bh3);
                    MMA16816(acc[mt][g * 2],     ah[mt], bl0, bl1);
                    MMA16816(acc[mt][g * 2 + 1], ah[mt], bl2, bl3);
                    MMA16816(acc[mt][g * 2],     al[mt], bh0, bh1);
                    MMA16816(acc[mt][g * 2 + 1], al[mt], bh2, bh3);
                }
            }
        }
    }

    // Epilogue (C stride = NOUT)
    const int qr = lane >> 2;
    const int qc = (lane & 3) * 2;
#pragma unroll
    for (int mt = 0; mt < 2; mt++) {
        const size_t r0e = mrow0 + wm * 32 + mt * 16 + qr;
        const int bb = (int)(r0e >> 11);
#pragma unroll
        for (int nt = 0; nt < 8; nt++) {
            const size_t col = nrow0 + wn * 64 + nt * 8 + qc;
            float a0 = acc[mt][nt][0], a1 = acc[mt][nt][1];
            float a2 = acc[mt][nt][2], a3 = acc[mt][nt][3];
            if (ADDY) {
                const float y0 = __ldg(yv + (size_t)bb * E_ + col);
                const float y1 = __ldg(yv + (size_t)bb * E_ + col + 1);
                a0 += y0; a1 += y1; a2 += y0; a3 += y1;
            }
            *(float2*)(C + r0e * NOUT + col)       = make_float2(a0, a1);
            *(float2*)(C + (r0e + 8) * NOUT + col) = make_float2(a2, a3);
        }
    }
}

// ---------------------------------------------------------------------------
// fp32 -> bf16 hi/lo split conversion (full width)
// ---------------------------------------------------------------------------
__global__ __launch_bounds__(256) void conv_split(
    const float* __restrict__ in, __nv_bfloat16* __restrict__ hi,
    __nv_bfloat16* __restrict__ lo, int n4)
{
    int idx = blockIdx.x * 256 + threadIdx.x;
    if (idx >= n4) return;
    float4 v = ((const float4*)in)[idx];
    __nv_bfloat16 h0 = __float2bfloat16(v.x), h1 = __float2bfloat16(v.y);
    __nv_bfloat16 h2 = __float2bfloat16(v.z), h3 = __float2bfloat16(v.w);
    __nv_bfloat16 l0 = __float2bfloat16(v.x - __bfloat162float(h0));
    __nv_bfloat16 l1 = __float2bfloat16(v.y - __bfloat162float(h1));
    __nv_bfloat16 l2 = __float2bfloat16(v.z - __bfloat162float(h2));
    __nv_bfloat16 l3 = __float2bfloat16(v.w - __bfloat162float(h3));
    __nv_bfloat162 hp0; hp0.x = h0; hp0.y = h1;
    __nv_bfloat162 hp1; hp1.x = h2; hp1.y = h3;
    __nv_bfloat162 lp0; lp0.x = l0; lp0.y = l1;
    __nv_bfloat162 lp1; lp1.x = l2; lp1.y = l3;
    uint2 hw, lw;
    hw.x = *(uint32_t*)&hp0; hw.y = *(uint32_t*)&hp1;
    lw.x = *(uint32_t*)&lp0; lw.y = *(uint32_t*)&lp1;
    ((uint2*)hi)[idx] = hw;
    ((uint2*)lo)[idx] = lw;
}

// ---------------------------------------------------------------------------
// W_in row-packed split: rows {0:384, 640:1024} -> [768, 1024]
// ---------------------------------------------------------------------------
__global__ __launch_bounds__(256) void conv_split_pack_rows(
    const float* __restrict__ in, __nv_bfloat16* __restrict__ hi,
    __nv_bfloat16* __restrict__ lo)
{
    int idx = blockIdx.x * 256 + threadIdx.x;   // over KP_*E_/4
    if (idx >= KP_ * E_ / 4) return;
    const int pos = idx * 4;
    const int np  = pos / E_;
    const int k   = pos % E_;
    const int n   = np < 384 ? np : np + 256;
    float4 v = *(const float4*)(in + (size_t)n * E_ + k);
    __nv_bfloat16 h0 = __float2bfloat16(v.x), h1 = __float2bfloat16(v.y);
    __nv_bfloat16 h2 = __float2bfloat16(v.z), h3 = __float2bfloat16(v.w);
    __nv_bfloat16 l0 = __float2bfloat16(v.x - __bfloat162float(h0));
    __nv_bfloat16 l1 = __float2bfloat16(v.y - __bfloat162float(h1));
    __nv_bfloat16 l2 = __float2bfloat16(v.z - __bfloat162float(h2));
    __nv_bfloat16 l3 = __float2bfloat16(v.w - __bfloat162float(h3));
    __nv_bfloat162 hp0; hp0.x = h0; hp0.y = h1;
    __nv_bfloat162 hp1; hp1.x = h2; hp1.y = h3;
    __nv_bfloat162 lp0; lp0.x = l0; lp0.y = l1;
    __nv_bfloat162 lp1; lp1.x = l2; lp1.y = l3;
    uint2 hw, lw;
    hw.x = *(uint32_t*)&hp0; hw.y = *(uint32_t*)&hp1;
    lw.x = *(uint32_t*)&lp0; lw.y = *(uint32_t*)&lp1;
    ((uint2*)hi)[idx] = hw;
    ((uint2*)lo)[idx] = lw;
}

// ---------------------------------------------------------------------------
// W_out col-packed split: cols {0:384, 640:1024} -> [1024, 768]
// ---------------------------------------------------------------------------
__global__ __launch_bounds__(256) void conv_split_pack(
    const float* __restrict__ in, __nv_bfloat16* __restrict__ hi,
    __nv_bfloat16* __restrict__ lo)
{
    int idx = blockIdx.x * 256 + threadIdx.x;   // over E_*KP_/4
    if (idx >= E_ * KP_ / 4) return;
    const int pos = idx * 4;
    const int n   = pos / KP_;
    const int kp  = pos % KP_;
    const int k   = kp < 384 ? kp : kp + 256;
    float4 v = *(const float4*)(in + (size_t)n * E_ + k);
    __nv_bfloat16 h0 = __float2bfloat16(v.x), h1 = __float2bfloat16(v.y);
    __nv_bfloat16 h2 = __float2bfloat16(v.z), h3 = __float2bfloat16(v.w);
    __nv_bfloat16 l0 = __float2bfloat16(v.x - __bfloat162float(h0));
    __nv_bfloat16 l1 = __float2bfloat16(v.y - __bfloat162float(h1));
    __nv_bfloat16 l2 = __float2bfloat16(v.z - __bfloat162float(h2));
    __nv_bfloat16 l3 = __float2bfloat16(v.w - __bfloat162float(h3));
    __nv_bfloat162 hp0; hp0.x = h0; hp0.y = h1;
    __nv_bfloat162 hp1; hp1.x = h2; hp1.y = h3;
    __nv_bfloat162 lp0; lp0.x = l0; lp0.y = l1;
    __nv_bfloat162 lp1; lp1.x = l2; lp1.y = l3;
    uint2 hw, lw;
    hw.x = *(uint32_t*)&hp0; hw.y = *(uint32_t*)&hp1;
    lw.x = *(uint32_t*)&lp0; lw.y = *(uint32_t*)&lp1;
    ((uint2*)hi)[idx] = hw;
    ((uint2*)lo)[idx] = lw;
}

__device__ __constant__ float c_wt[RAD + 1] = {
    1.0f, 0.60653066f, 0.13533528f, 0.011108997f, 3.3546263e-4f, 3.7266532e-6f};

// ---------------------------------------------------------------------------
// Gaussian smoothing on packed V [M,768] -> packed bf16 U [M,768].
// ---------------------------------------------------------------------------
__global__ __launch_bounds__(192) void smooth_pack(
    const float* __restrict__ V, __nv_bfloat16* __restrict__ Uh,
    __nv_bfloat16* __restrict__ Ul)
{
    const int n = blockIdx.x;        // b*L + q
    const int b = n >> 11;
    const int q = n & (L_ - 1);
    const int kp = threadIdx.x * 4;  // packed col
    const int hp = kp >> 7;          // 0..5

    int c;
    switch (hp % 3) {
        case 0:  c = q;     break;   // center
        case 1:  c = q - 1; break;   // left
        default: c = q + 1; break;   // right
    }

    float ax = 0.f, ay = 0.f, az = 0.f, aw = 0.f, wsum = 0.f;
#pragma unroll
    for (int d = -RAD; d <= RAD; d++) {
        const int j = c + d;
        if (j >= 0 && j < L_) {
            const float w = c_wt[d < 0 ? -d : d];
            wsum += w;
            const float4 v = *(const float4*)(V + ((size_t)b * L_ + j) * KP_ + kp);
            ax = fmaf(w, v.x, ax); ay = fmaf(w, v.y, ay);
            az = fmaf(w, v.z, az); aw = fmaf(w, v.w, aw);
        }
    }
    const float inv = 1.0f / wsum;
    ax *= inv; ay *= inv; az *= inv; aw *= inv;

    __nv_bfloat16 h0 = __float2bfloat16(ax), h1 = __float2bfloat16(ay);
    __nv_bfloat16 h2 = __float2bfloat16(az), h3 = __float2bfloat16(aw);
    __nv_bfloat16 l0 = __float2bfloat16(ax - __bfloat162float(h0));
    __nv_bfloat16 l1 = __float2bfloat16(ay - __bfloat162float(h1));
    __nv_bfloat16 l2 = __float2bfloat16(az - __bfloat162float(h2));
    __nv_bfloat16 l3 = __float2bfloat16(aw - __bfloat162float(h3));
    __nv_bfloat162 hp0; hp0.x = h0; hp0.y = h1;
    __nv_bfloat162 hp1; hp1.x = h2; hp1.y = h3;
    __nv_bfloat162 lp0; lp0.x = l0; lp0.y = l1;
    __nv_bfloat162 lp1; lp1.x = l2; lp1.y = l3;
    uint2 hw, lw;
    hw.x = *(uint32_t*)&hp0; hw.y = *(uint32_t*)&hp1;
    lw.x = *(uint32_t*)&lp0; lw.y = *(uint32_t*)&lp1;
    const size_t o = ((size_t)n * KP_ + kp) >> 2;
    ((uint2*)Uh)[o] = hw;
    ((uint2*)Ul)[o] = lw;
}

// ---------------------------------------------------------------------------
// xbar[(b,h)][k] = renormalized Gaussian combination of 6 edge rows of x.
// h=0: 'first' (rows 0..5), h=1: 'last' (rows L-1-d). Coalesced over k.
// ---------------------------------------------------------------------------
__global__ __launch_bounds__(256) void xbar_kernel(
    const float* __restrict__ x, float* __restrict__ xbar)
{
    const int b = blockIdx.x >> 1;
    const int h = blockIdx.x & 1;
    float wsum = 0.f;
#pragma unroll
    for (int d = 0; d <= RAD; d++) wsum += c_wt[d];
    const float inv = 1.0f / wsum;
    for (int k = threadIdx.x; k < E_; k += 256) {
        float acc = 0.f;
#pragma unroll
        for (int d = 0; d <= RAD; d++) {
            const int j = h ? (L_ - 1 - d) : d;
            acc = fmaf(c_wt[d], x[((size_t)b * L_ + j) * E_ + k], acc);
        }
        xbar[(size_t)blockIdx.x * E_ + k] = acc * inv;
    }
}

// ---------------------------------------------------------------------------
// ubar[b][p] = xbar[(b, p>=128)] . W_in[384+p, :]  — warp-per-dot, lane-split
// over K (coalesced), shuffle reduce. 2048 dots; grid 256 x 256thr.
// ---------------------------------------------------------------------------
__global__ __launch_bounds__(256) void ubar_kernel(
    const float* __restrict__ xbar, const float* __restrict__ W_in,
    float* __restrict__ ubar)
{
    const int idx  = blockIdx.x * 8 + (threadIdx.x >> 5);   // 0..2047
    const int lane = threadIdx.x & 31;
    const int b = idx >> 8;
    const int p = idx & 255;
    const float* xb = xbar + (size_t)(b * 2 + (p >= 128 ? 1 : 0)) * E_;
    const float* wr = W_in + (size_t)(384 + p) * E_;
    float acc = 0.f;
#pragma unroll 8
    for (int k = lane; k < E_; k += 32) acc = fmaf(xb[k], wr[k], acc);
#pragma unroll
    for (int o = 16; o > 0; o >>= 1) acc += __shfl_xor_sync(0xFFFFFFFFu, acc, o);
    if (lane == 0) ubar[b * 256 + p] = acc;
}

// ---------------------------------------------------------------------------
// y[b][n] = ubar[b] . W_out[n, 384:640] — warp-per-dot (coalesced), 8192 dots.
// ---------------------------------------------------------------------------
__global__ __launch_bounds__(256) void yvec_kernel(
    const float* __restrict__ ubar, const float* __restrict__ Wout,
    float* __restrict__ yv)
{
    const int idx  = blockIdx.x * 8 + (threadIdx.x >> 5);   // 0..8191
    const int lane = threadIdx.x & 31;
    const int b = idx >> 10;
    const int n = idx & 1023;
    const float* ub = ubar + b * 256;
    const float* wr = Wout + (size_t)n * E_ + 384;
    float acc = 0.f;
#pragma unroll
    for (int i = 0; i < 8; i++) {
        const int p = lane + i * 32;
        acc = fmaf(ub[p], wr[p], acc);
    }
#pragma unroll
    for (int o = 16; o > 0; o >>= 1) acc += __shfl_xor_sync(0xFFFFFFFFu, acc, o);
    if (lane == 0) yv[b * E_ + n] = acc;
}

// ---------------------------------------------------------------------------
extern "C" void kernel_launch(void* const* d_in, const int* in_sizes, int n_in,
                              void* d_out, int out_size)
{
    (void)in_sizes; (void)n_in; (void)out_size;
    const float* x     = (const float*)d_in[0];
    const float* W_in  = (const float*)d_in[1];
    const float* W_out = (const float*)d_in[2];
    float* out = (float*)d_out;

    __nv_bfloat16 *Xh, *Xl, *Wih, *Wil, *Wph, *Wpl, *Uh, *Ul;
    float *Vf, *xbar, *ubar, *yv;
    cudaGetSymbolAddress((void**)&Xh, g_Xh);
    cudaGetSymbolAddress((void**)&Xl, g_Xl);
    cudaGetSymbolAddress((void**)&Wih, g_Wih);
    cudaGetSymbolAddress((void**)&Wil, g_Wil);
    cudaGetSymbolAddress((void**)&Wph, g_Wph);
    cudaGetSymbolAddress((void**)&Wpl, g_Wpl);
    cudaGetSymbolAddress((void**)&Vf, g_Vf);
    cudaGetSymbolAddress((void**)&Uh, g_Uh);
    cudaGetSymbolAddress((void**)&Ul, g_Ul);
    cudaGetSymbolAddress((void**)&xbar, g_xbar);
    cudaGetSymbolAddress((void**)&ubar, g_ubar);
    cudaGetSymbolAddress((void**)&yv, g_yv);

    cudaFuncSetAttribute((const void*)gemm_mma<E_, KP_, false>,
                         cudaFuncAttributeMaxDynamicSharedMemorySize, SM_TOTAL);
    cudaFuncSetAttribute((const void*)gemm_mma<KP_, E_, true>,
                         cudaFuncAttributeMaxDynamicSharedMemorySize, SM_TOTAL);

    // Split conversions
    conv_split<<<(M_ * E_ / 4 + 255) / 256, 256>>>(x, Xh, Xl, M_ * E_ / 4);
    conv_split_pack_rows<<<(KP_ * E_ / 4 + 255) / 256, 256>>>(W_in, Wih, Wil);
    conv_split_pack<<<(E_ * KP_ / 4 + 255) / 256, 256>>>(W_out, Wph, Wpl);

    // const-head path (exact fp32 from raw inputs; coalesced warp-dots)
    xbar_kernel<<<16, 256>>>(x, xbar);
    ubar_kernel<<<256, 256>>>(xbar, W_in, ubar);
    yvec_kernel<<<1024, 256>>>(ubar, W_out, yv);

    // Vp = X @ W_in_packed^T  (fp32, [M,768])
    dim3 grid1(KP_ / GBN, M_ / GBM);   // (6, 128)
    gemm_mma<E_, KP_, false><<<grid1, 256, SM_TOTAL>>>(Xh, Xl, Wih, Wil, Vf, nullptr);

    // U (packed) = gaussian smooth of Vp
    smooth_pack<<<M_, 192>>>(Vf, Uh, Ul);

    // out = U_packed @ W_out_packed^T + broadcast(yv)
    dim3 grid2(E_ / GBN, M_ / GBM);    // (8, 128)
    gemm_mma<KP_, E_, true><<<grid2, 256, SM_TOTAL>>>(Uh, Ul, Wph, Wpl, out, yv);
}

// round 16
// speedup vs baseline: 1.5422x; 1.1418x over previous
#include <cuda_runtime.h>
#include <cuda_bf16.h>
#include <cstdint>

// Problem dims (fixed)
#define B_   8
#define L_   2048
#define E_   1024
#define M_   (B_ * L_)   // 16384
#define RAD  5
#define KP_  768         // packed width (heads 3,4 'first'/'last' removed)

// ---------------------------------------------------------------------------
// Scratch (__device__ globals; allocation-free rule)
// ---------------------------------------------------------------------------
__device__ float         g_Wit[(size_t)KP_ * E_];   // W_in rows packed, tf32-rounded fp32
__device__ __nv_bfloat16 g_Wph[(size_t)E_ * KP_];   // W_out cols packed [1024,768]
__device__ __nv_bfloat16 g_Wpl[(size_t)E_ * KP_];
__device__ float         g_Vf [(size_t)M_ * KP_];   // packed V [M,768]
__device__ __nv_bfloat16 g_Uh[(size_t)M_ * KP_];    // packed U [M,768]
__device__ __nv_bfloat16 g_Ul[(size_t)M_ * KP_];
__device__ float         g_xbar[16 * E_];           // weighted x rows (b,h)
__device__ float         g_ubar[B_ * 256];          // per-batch const-head values
__device__ float         g_yv[B_ * E_];             // per-batch broadcast output

__device__ __forceinline__ uint32_t smem_u32(const void* p) {
    uint32_t a;
    asm("{ .reg .u64 t; cvta.to.shared.u64 t, %1; cvt.u32.u64 %0, t; }" : "=r"(a) : "l"(p));
    return a;
}

#define CP_ASYNC16(dst, src) \
    asm volatile("cp.async.cg.shared.global [%0], [%1], 16;" :: "r"(dst), "l"(src))
#define CP_COMMIT() asm volatile("cp.async.commit_group;")
#define CP_WAIT(n)  asm volatile("cp.async.wait_group %0;" :: "n"(n))

#define LDSM_X4(r0, r1, r2, r3, addr)                                        \
    asm volatile("ldmatrix.sync.aligned.m8n8.x4.shared.b16 {%0,%1,%2,%3}, [%4];" \
                 : "=r"(r0), "=r"(r1), "=r"(r2), "=r"(r3) : "r"(addr))

#define MMA16816(acc, ar, b0, b1)                                            \
    asm volatile("mma.sync.aligned.m16n8k16.row.col.f32.bf16.bf16.f32 "      \
                 "{%0,%1,%2,%3}, {%4,%5,%6,%7}, {%8,%9}, {%0,%1,%2,%3};"     \
                 : "+f"((acc)[0]), "+f"((acc)[1]), "+f"((acc)[2]), "+f"((acc)[3]) \
                 : "r"((ar)[0]), "r"((ar)[1]), "r"((ar)[2]), "r"((ar)[3]),   \
                   "r"(b0), "r"(b1))

#define MMA1688_TF32(acc, a0, a1, a2, a3, b0, b1)                            \
    asm volatile("mma.sync.aligned.m16n8k8.row.col.f32.tf32.tf32.f32 "       \
                 "{%0,%1,%2,%3}, {%4,%5,%6,%7}, {%8,%9}, {%0,%1,%2,%3};"     \
                 : "+f"((acc)[0]), "+f"((acc)[1]), "+f"((acc)[2]), "+f"((acc)[3]) \
                 : "r"(a0), "r"(a1), "r"(a2), "r"(a3), "r"(b0), "r"(b1))

#define LDS32(r, addr) \
    asm volatile("ld.shared.b32 %0, [%1];" : "=r"(r) : "r"(addr))
#define CVT_TF32(r) \
    asm volatile("cvt.rna.tf32.f32 %0, %0;" : "+r"(r))

// ===========================================================================
// GEMM1 (tf32 single-pass): V[M, KP_] = X[M,1024] @ Wt[KP_,1024]^T
// BM=BN=128, BK=32 (fp32 tiles, 16KB each), 256 thr, warp tile 32x64,
// 3-stage cp.async (32KB/stage), 2 CTAs/SM.
// smem layout: rows of 128B (32 fp32), 16B-seg swizzle: seg*16 ^ (row&7)*16.
// A loaded raw fp32 and cvt.rna'd in-register; B pre-rounded to tf32.
// ===========================================================================
#define G1_TA 0
#define G1_TB 16384
#define G1_STG 32768
#define G1_SMEM (3 * G1_STG)   // 98304

__global__ __launch_bounds__(256, 2) void gemm_tf32(
    const float* __restrict__ A, const float* __restrict__ Bt,
    float* __restrict__ C)
{
    const int NCHUNK = E_ / 32;   // 32
    extern __shared__ char smem[];
    const uint32_t smem_base = smem_u32(smem);

    const int tid  = threadIdx.x;
    const int wid  = tid >> 5;
    const int lane = tid & 31;
    const int wm   = wid & 3;    // M offset wm*32
    const int wn   = wid >> 2;   // N offset wn*64

    const size_t mrow0 = (size_t)blockIdx.y * 128;
    const size_t nrow0 = (size_t)blockIdx.x * 128;

    // cp.async mapping: per rep, u = tid + rep*256 (0..1023): row=u>>3, seg=u&7
    uint32_t so[4];
    const float *gA[4], *gB[4];
#pragma unroll
    for (int rep = 0; rep < 4; rep++) {
        const int u = tid + rep * 256;
        const int row = u >> 3, seg = u & 7;
        so[rep] = (uint32_t)row * 128 + (uint32_t)((seg * 16) ^ ((row & 7) * 16));
        gA[rep] = A  + (mrow0 + row) * E_ + seg * 4;
        gB[rep] = Bt + (nrow0 + row) * E_ + seg * 4;
    }

    // fragment lane addressing
    const int lr = lane >> 2;          // 0..7
    const int lc = lane & 3;           // 0..3
    const uint32_t rswz = (uint32_t)lr * 16;
    uint32_t aBase[2];
#pragma unroll
    for (int mt = 0; mt < 2; mt++)
        aBase[mt] = (uint32_t)(wm * 32 + mt * 16 + lr) * 128 + lc * 4;
    uint32_t bBase[8];
#pragma unroll
    for (int g = 0; g < 8; g++)
        bBase[g] = (uint32_t)(wn * 64 + g * 8 + lr) * 128 + lc * 4;

    float acc[2][8][4];
#pragma unroll
    for (int mt = 0; mt < 2; mt++)
#pragma unroll
        for (int nt = 0; nt < 8; nt++)
#pragma unroll
            for (int r = 0; r < 4; r++) acc[mt][nt][r] = 0.0f;

    auto load_chunk = [&](int ch, int stg) {
        const uint32_t sb = smem_base + (uint32_t)stg * G1_STG;
        const int kb = ch * 32;
#pragma unroll
        for (int rep = 0; rep < 4; rep++) {
            CP_ASYNC16(sb + G1_TA + so[rep], gA[rep] + kb);
            CP_ASYNC16(sb + G1_TB + so[rep], gB[rep] + kb);
        }
        CP_COMMIT();
    };

    load_chunk(0, 0);
    load_chunk(1, 1);

#pragma unroll 1
    for (int ch = 0; ch < NCHUNK; ch++) {
        if (ch + 1 < NCHUNK) { CP_WAIT(1); } else { CP_WAIT(0); }
        __syncthreads();
        if (ch + 2 < NCHUNK) load_chunk(ch + 2, (ch + 2) % 3);

        const uint32_t sb = smem_base + (uint32_t)(ch % 3) * G1_STG;
#pragma unroll
        for (int ks = 0; ks < 4; ks++) {
            const uint32_t k0 = (uint32_t)(ks * 32) ^ rswz;          // seg 2ks
            const uint32_t k1 = (uint32_t)(ks * 32 + 16) ^ rswz;     // seg 2ks+1
            // A fragments (raw fp32 -> tf32 round)
            uint32_t a[2][4];
#pragma unroll
            for (int mt = 0; mt < 2; mt++) {
                const uint32_t b0a = sb + G1_TA + aBase[mt];
                LDS32(a[mt][0], b0a + k0);
                LDS32(a[mt][1], b0a + k0 + 1024);   // row +8
                LDS32(a[mt][2], b0a + k1);
                LDS32(a[mt][3], b0a + k1 + 1024);
                CVT_TF32(a[mt][0]); CVT_TF32(a[mt][1]);
                CVT_TF32(a[mt][2]); CVT_TF32(a[mt][3]);
            }
#pragma unroll
            for (int g = 0; g < 8; g++) {
                uint32_t b0, b1;
                const uint32_t bb = sb + G1_TB + bBase[g];
                LDS32(b0, bb + k0);
                LDS32(b1, bb + k1);
                MMA1688_TF32(acc[0][g], a[0][0], a[0][1], a[0][2], a[0][3], b0, b1);
                MMA1688_TF32(acc[1][g], a[1][0], a[1][1], a[1][2], a[1][3], b0, b1);
            }
        }
    }

    // Epilogue: C stride KP_
    const int qr = lane >> 2;
    const int qc = (lane & 3) * 2;
#pragma unroll
    for (int mt = 0; mt < 2; mt++) {
        const size_t r0e = mrow0 + wm * 32 + mt * 16 + qr;
#pragma unroll
        for (int nt = 0; nt < 8; nt++) {
            const size_t col = nrow0 + wn * 64 + nt * 8 + qc;
            *(float2*)(C + r0e * KP_ + col)       = make_float2(acc[mt][nt][0], acc[mt][nt][1]);
            *(float2*)(C + (r0e + 8) * KP_ + col) = make_float2(acc[mt][nt][2], acc[mt][nt][3]);
        }
    }
}

// ===========================================================================
// GEMM2 (bf16 3-split, unchanged): out[M,1024] = U[M,768] @ Wp[1024,768]^T (+yv)
// ===========================================================================
#define GBM 128
#define GBN 128
#define GBK 32

#define T_AH 0
#define T_AL 8192
#define T_WH 16384
#define T_WL 24576
#define STG_BYTES 32768
#define SM_TOTAL (3 * STG_BYTES)

__global__ __launch_bounds__(256, 2) void gemm_mma(
    const __nv_bfloat16* __restrict__ Ah, const __nv_bfloat16* __restrict__ Al,
    const __nv_bfloat16* __restrict__ Wh, const __nv_bfloat16* __restrict__ Wl,
    float* __restrict__ C, const float* __restrict__ yv)
{
    const int KD = KP_;
    const int NCHUNK = KD / GBK;   // 24
    extern __shared__ char smem[];
    const uint32_t smem_base = smem_u32(smem);

    const int tid  = threadIdx.x;
    const int wid  = tid >> 5;
    const int lane = tid & 31;
    const int wm   = wid & 3;
    const int wn   = wid >> 2;

    const size_t mrow0 = (size_t)blockIdx.y * GBM;
    const size_t nrow0 = (size_t)blockIdx.x * GBN;

    const int r0 = tid >> 2;
    const int r1 = r0 + 64;
    const int sg = tid & 3;
    const uint32_t so0 = (uint32_t)r0 * 64 + (uint32_t)((sg * 16) ^ (((r0 >> 1) & 3) << 4));
    const uint32_t so1 = (uint32_t)r1 * 64 + (uint32_t)((sg * 16) ^ (((r1 >> 1) & 3) << 4));
    const __nv_bfloat16* gAh0 = Ah + (mrow0 + r0) * KD + sg * 8;
    const __nv_bfloat16* gAh1 = Ah + (mrow0 + r1) * KD + sg * 8;
    const __nv_bfloat16* gAl0 = Al + (mrow0 + r0) * KD + sg * 8;
    const __nv_bfloat16* gAl1 = Al + (mrow0 + r1) * KD + sg * 8;
    const __nv_bfloat16* gWh0 = Wh + (nrow0 + r0) * KD + sg * 8;
    const __nv_bfloat16* gWh1 = Wh + (nrow0 + r1) * KD + sg * 8;
    const __nv_bfloat16* gWl0 = Wl + (nrow0 + r0) * KD + sg * 8;
    const __nv_bfloat16* gWl1 = Wl + (nrow0 + r1) * KD + sg * 8;

    uint32_t aBase[2], aSwz[2];
#pragma unroll
    for (int mt = 0; mt < 2; mt++) {
        const int r = wm * 32 + mt * 16 + (lane & 15);
        aBase[mt] = (uint32_t)r * 64;
        aSwz[mt]  = (uint32_t)(((r >> 1) & 3) << 4);
    }
    const uint32_t cselA = (uint32_t)(((lane >> 4) & 1) * 16);
    uint32_t bBase[4], bSwz[4];
#pragma unroll
    for (int g = 0; g < 4; g++) {
        const int r = wn * 64 + g * 16 + (lane & 7) + ((lane >> 4) & 1) * 8;
        bBase[g] = (uint32_t)r * 64;
        bSwz[g]  = (uint32_t)(((r >> 1) & 3) << 4);
    }
    const uint32_t cselB = (uint32_t)(((lane >> 3) & 1) * 16);

    float acc[2][8][4];
#pragma unroll
    for (int mt = 0; mt < 2; mt++)
#pragma unroll
        for (int nt = 0; nt < 8; nt++)
#pragma unroll
            for (int r = 0; r < 4; r++) acc[mt][nt][r] = 0.0f;

    auto load_chunk = [&](int ch, int stg) {
        const uint32_t sb = smem_base + (uint32_t)stg * STG_BYTES;
        const int kb = ch * GBK;
        CP_ASYNC16(sb + T_AH + so0, gAh0 + kb);
        CP_ASYNC16(sb + T_AH + so1, gAh1 + kb);
        CP_ASYNC16(sb + T_AL + so0, gAl0 + kb);
        CP_ASYNC16(sb + T_AL + so1, gAl1 + kb);
        CP_ASYNC16(sb + T_WH + so0, gWh0 + kb);
        CP_ASYNC16(sb + T_WH + so1, gWh1 + kb);
        CP_ASYNC16(sb + T_WL + so0, gWl0 + kb);
        CP_ASYNC16(sb + T_WL + so1, gWl1 + kb);
        CP_COMMIT();
    };

    load_chunk(0, 0);
    load_chunk(1, 1);

#pragma unroll 1
    for (int ch = 0; ch < NCHUNK; ch++) {
        if (ch + 1 < NCHUNK) { CP_WAIT(1); } else { CP_WAIT(0); }
        __syncthreads();
        if (ch + 2 < NCHUNK) load_chunk(ch + 2, (ch + 2) % 3);

        const uint32_t sb = smem_base + (uint32_t)(ch % 3) * STG_BYTES;
#pragma unroll
        for (int ks = 0; ks < 2; ks++) {
            const uint32_t kb = (uint32_t)(ks * 32);
            uint32_t ah[2][4], al[2][4];
#pragma unroll
            for (int mt = 0; mt < 2; mt++) {
                const uint32_t off = aBase[mt] + ((kb + cselA) ^ aSwz[mt]);
                LDSM_X4(ah[mt][0], ah[mt][1], ah[mt][2], ah[mt][3], sb + T_AH + off);
                LDSM_X4(al[mt][0], al[mt][1], al[mt][2], al[mt][3], sb + T_AL + off);
            }
#pragma unroll
            for (int g = 0; g < 4; g++) {
                const uint32_t boff = bBase[g] + ((kb + cselB) ^ bSwz[g]);
                uint32_t bh0, bh1, bh2, bh3, bl0, bl1, bl2, bl3;
                LDSM_X4(bh0, bh1, bh2, bh3, sb + T_WH + boff);
                LDSM_X4(bl0, bl1, bl2, bl3, sb + T_WL + boff);
#pragma unroll
                for (int mt = 0; mt < 2; mt++) {
                    MMA16816(acc[mt][g * 2],     ah[mt], bh0, bh1);
                    MMA16816(acc[mt][g * 2 + 1], ah[mt], bh2, bh3);
                    MMA16816(acc[mt][g * 2],     ah[mt], bl0, bl1);
                    MMA16816(acc[mt][g * 2 + 1], ah[mt], bl2, bl3);
                    MMA16816(acc[mt][g * 2],     al[mt], bh0, bh1);
                    MMA16816(acc[mt][g * 2 + 1], al[mt], bh2, bh3);
                }
            }
        }
    }

    const int qr = lane >> 2;
    const int qc = (lane & 3) * 2;
#pragma unroll
    for (int mt = 0; mt < 2; mt++) {
        const size_t r0e = mrow0 + wm * 32 + mt * 16 + qr;
        const int bb = (int)(r0e >> 11);
#pragma unroll
        for (int nt = 0; nt < 8; nt++) {
            const size_t col = nrow0 + wn * 64 + nt * 8 + qc;
            float a0 = acc[mt][nt][0], a1 = acc[mt][nt][1];
            float a2 = acc[mt][nt][2], a3 = acc[mt][nt][3];
            const float y0 = __ldg(yv + (size_t)bb * E_ + col);
            const float y1 = __ldg(yv + (size_t)bb * E_ + col + 1);
            a0 += y0; a1 += y1; a2 += y0; a3 += y1;
            *(float2*)(C + r0e * E_ + col)       = make_float2(a0, a1);
            *(float2*)(C + (r0e + 8) * E_ + col) = make_float2(a2, a3);
        }
    }
}

// ---------------------------------------------------------------------------
// W_in row-packed tf32 rounding: rows {0:384, 640:1024} -> fp32(tf32) [768,1024]
// ---------------------------------------------------------------------------
__global__ __launch_bounds__(256) void round_pack_rows_tf32(
    const float* __restrict__ in, float* __restrict__ outp)
{
    int idx = blockIdx.x * 256 + threadIdx.x;   // over KP_*E_/4
    if (idx >= KP_ * E_ / 4) return;
    const int pos = idx * 4;
    const int np  = pos / E_;
    const int k   = pos % E_;
    const int n   = np < 384 ? np : np + 256;
    float4 v = *(const float4*)(in + (size_t)n * E_ + k);
    uint32_t u0 = __float_as_uint(v.x), u1 = __float_as_uint(v.y);
    uint32_t u2 = __float_as_uint(v.z), u3 = __float_as_uint(v.w);
    CVT_TF32(u0); CVT_TF32(u1); CVT_TF32(u2); CVT_TF32(u3);
    float4 o;
    o.x = __uint_as_float(u0); o.y = __uint_as_float(u1);
    o.z = __uint_as_float(u2); o.w = __uint_as_float(u3);
    ((float4*)outp)[idx] = o;
}

// ---------------------------------------------------------------------------
// W_out col-packed split: cols {0:384, 640:1024} -> bf16 hi/lo [1024, 768]
// ---------------------------------------------------------------------------
__global__ __launch_bounds__(256) void conv_split_pack(
    const float* __restrict__ in, __nv_bfloat16* __restrict__ hi,
    __nv_bfloat16* __restrict__ lo)
{
    int idx = blockIdx.x * 256 + threadIdx.x;
    if (idx >= E_ * KP_ / 4) return;
    const int pos = idx * 4;
    const int n   = pos / KP_;
    const int kp  = pos % KP_;
    const int k   = kp < 384 ? kp : kp + 256;
    float4 v = *(const float4*)(in + (size_t)n * E_ + k);
    __nv_bfloat16 h0 = __float2bfloat16(v.x), h1 = __float2bfloat16(v.y);
    __nv_bfloat16 h2 = __float2bfloat16(v.z), h3 = __float2bfloat16(v.w);
    __nv_bfloat16 l0 = __float2bfloat16(v.x - __bfloat162float(h0));
    __nv_bfloat16 l1 = __float2bfloat16(v.y - __bfloat162float(h1));
    __nv_bfloat16 l2 = __float2bfloat16(v.z - __bfloat162float(h2));
    __nv_bfloat16 l3 = __float2bfloat16(v.w - __bfloat162float(h3));
    __nv_bfloat162 hp0; hp0.x = h0; hp0.y = h1;
    __nv_bfloat162 hp1; hp1.x = h2; hp1.y = h3;
    __nv_bfloat162 lp0; lp0.x = l0; lp0.y = l1;
    __nv_bfloat162 lp1; lp1.x = l2; lp1.y = l3;
    uint2 hw, lw;
    hw.x = *(uint32_t*)&hp0; hw.y = *(uint32_t*)&hp1;
    lw.x = *(uint32_t*)&lp0; lw.y = *(uint32_t*)&lp1;
    ((uint2*)hi)[idx] = hw;
    ((uint2*)lo)[idx] = lw;
}

__device__ __constant__ float c_wt[RAD + 1] = {
    1.0f, 0.60653066f, 0.13533528f, 0.011108997f, 3.3546263e-4f, 3.7266532e-6f};

// ---------------------------------------------------------------------------
// Gaussian smoothing on packed V [M,768] -> packed bf16 U [M,768].
// ---------------------------------------------------------------------------
__global__ __launch_bounds__(192) void smooth_pack(
    const float* __restrict__ V, __nv_bfloat16* __restrict__ Uh,
    __nv_bfloat16* __restrict__ Ul)
{
    const int n = blockIdx.x;
    const int b = n >> 11;
    const int q = n & (L_ - 1);
    const int kp = threadIdx.x * 4;
    const int hp = kp >> 7;

    int c;
    switch (hp % 3) {
        case 0:  c = q;     break;
        case 1:  c = q - 1; break;
        default: c = q + 1; break;
    }

    float ax = 0.f, ay = 0.f, az = 0.f, aw = 0.f, wsum = 0.f;
#pragma unroll
    for (int d = -RAD; d <= RAD; d++) {
        const int j = c + d;
        if (j >= 0 && j < L_) {
            const float w = c_wt[d < 0 ? -d : d];
            wsum += w;
            const float4 v = *(const float4*)(V + ((size_t)b * L_ + j) * KP_ + kp);
            ax = fmaf(w, v.x, ax); ay = fmaf(w, v.y, ay);
            az = fmaf(w, v.z, az); aw = fmaf(w, v.w, aw);
        }
    }
    const float inv = 1.0f / wsum;
    ax *= inv; ay *= inv; az *= inv; aw *= inv;

    __nv_bfloat16 h0 = __float2bfloat16(ax), h1 = __float2bfloat16(ay);
    __nv_bfloat16 h2 = __float2bfloat16(az), h3 = __float2bfloat16(aw);
    __nv_bfloat16 l0 = __float2bfloat16(ax - __bfloat162float(h0));
    __nv_bfloat16 l1 = __float2bfloat16(ay - __bfloat162float(h1));
    __nv_bfloat16 l2 = __float2bfloat16(az - __bfloat162float(h2));
    __nv_bfloat16 l3 = __float2bfloat16(aw - __bfloat162float(h3));
    __nv_bfloat162 hp0; hp0.x = h0; hp0.y = h1;
    __nv_bfloat162 hp1; hp1.x = h2; hp1.y = h3;
    __nv_bfloat162 lp0; lp0.x = l0; lp0.y = l1;
    __nv_bfloat162 lp1; lp1.x = l2; lp1.y = l3;
    uint2 hw, lw;
    hw.x = *(uint32_t*)&hp0; hw.y = *(uint32_t*)&hp1;
    lw.x = *(uint32_t*)&lp0; lw.y = *(uint32_t*)&lp1;
    const size_t o = ((size_t)n * KP_ + kp) >> 2;
    ((uint2*)Uh)[o] = hw;
    ((uint2*)Ul)[o] = lw;
}

// ---------------------------------------------------------------------------
// xbar / ubar / yvec: exact fp32 const-head path (coalesced warp dots)
// ---------------------------------------------------------------------------
__global__ __launch_bounds__(256) void xbar_kernel(
    const float* __restrict__ x, float* __restrict__ xbar)
{
    const int b = blockIdx.x >> 1;
    const int h = blockIdx.x & 1;
    float wsum = 0.f;
#pragma unroll
    for (int d = 0; d <= RAD; d++) wsum += c_wt[d];
    const float inv = 1.0f / wsum;
    for (int k = threadIdx.x; k < E_; k += 256) {
        float acc = 0.f;
#pragma unroll
        for (int d = 0; d <= RAD; d++) {
            const int j = h ? (L_ - 1 - d) : d;
            acc = fmaf(c_wt[d], x[((size_t)b * L_ + j) * E_ + k], acc);
        }
        xbar[(size_t)blockIdx.x * E_ + k] = acc * inv;
    }
}

__global__ __launch_bounds__(256) void ubar_kernel(
    const float* __restrict__ xbar, const float* __restrict__ W_in,
    float* __restrict__ ubar)
{
    const int idx  = blockIdx.x * 8 + (threadIdx.x >> 5);
    const int lane = threadIdx.x & 31;
    const int b = idx >> 8;
    const int p = idx & 255;
    const float* xb = xbar + (size_t)(b * 2 + (p >= 128 ? 1 : 0)) * E_;
    const float* wr = W_in + (size_t)(384 + p) * E_;
    float acc = 0.f;
#pragma unroll 8
    for (int k = lane; k < E_; k += 32) acc = fmaf(xb[k], wr[k], acc);
#pragma unroll
    for (int o = 16; o > 0; o >>= 1) acc += __shfl_xor_sync(0xFFFFFFFFu, acc, o);
    if (lane == 0) ubar[b * 256 + p] = acc;
}

__global__ __launch_bounds__(256) void yvec_kernel(
    const float* __restrict__ ubar, const float* __restrict__ Wout,
    float* __restrict__ yv)
{
    const int idx  = blockIdx.x * 8 + (threadIdx.x >> 5);
    const int lane = threadIdx.x & 31;
    const int b = idx >> 10;
    const int n = idx & 1023;
    const float* ub = ubar + b * 256;
    const float* wr = Wout + (size_t)n * E_ + 384;
    float acc = 0.f;
#pragma unroll
    for (int i = 0; i < 8; i++) {
        const int p = lane + i * 32;
        acc = fmaf(ub[p], wr[p], acc);
    }
#pragma unroll
    for (int o = 16; o > 0; o >>= 1) acc += __shfl_xor_sync(0xFFFFFFFFu, acc, o);
    if (lane == 0) yv[b * E_ + n] = acc;
}

// ---------------------------------------------------------------------------
extern "C" void kernel_launch(void* const* d_in, const int* in_sizes, int n_in,
                              void* d_out, int out_size)
{
    (void)in_sizes; (void)n_in; (void)out_size;
    const float* x     = (const float*)d_in[0];
    const float* W_in  = (const float*)d_in[1];
    const float* W_out = (const float*)d_in[2];
    float* out = (float*)d_out;

    __nv_bfloat16 *Wph, *Wpl, *Uh, *Ul;
    float *Wit, *Vf, *xbar, *ubar, *yv;
    cudaGetSymbolAddress((void**)&Wit, g_Wit);
    cudaGetSymbolAddress((void**)&Wph, g_Wph);
    cudaGetSymbolAddress((void**)&Wpl, g_Wpl);
    cudaGetSymbolAddress((void**)&Vf, g_Vf);
    cudaGetSymbolAddress((void**)&Uh, g_Uh);
    cudaGetSymbolAddress((void**)&Ul, g_Ul);
    cudaGetSymbolAddress((void**)&xbar, g_xbar);
    cudaGetSymbolAddress((void**)&ubar, g_ubar);
    cudaGetSymbolAddress((void**)&yv, g_yv);

    cudaFuncSetAttribute(gemm_tf32, cudaFuncAttributeMaxDynamicSharedMemorySize, G1_SMEM);
    cudaFuncSetAttribute(gemm_mma,  cudaFuncAttributeMaxDynamicSharedMemorySize, SM_TOTAL);

    // Weight prep
    round_pack_rows_tf32<<<(KP_ * E_ / 4 + 255) / 256, 256>>>(W_in, Wit);
    conv_split_pack<<<(E_ * KP_ / 4 + 255) / 256, 256>>>(W_out, Wph, Wpl);

    // const-head path (exact fp32)
    xbar_kernel<<<16, 256>>>(x, xbar);
    ubar_kernel<<<256, 256>>>(xbar, W_in, ubar);
    yvec_kernel<<<1024, 256>>>(ubar, W_out, yv);

    // Vp = X @ W_in_packed^T  (tf32 single-pass, fp32 out [M,768])
    dim3 grid1(KP_ / 128, M_ / 128);   // (6, 128)
    gemm_tf32<<<grid1, 256, G1_SMEM>>>(x, Wit, Vf);

    // U (packed) = gaussian smooth of Vp
    smooth_pack<<<M_, 192>>>(Vf, Uh, Ul);

    // out = U_packed @ W_out_packed^T + broadcast(yv)
    dim3 grid2(E_ / GBN, M_ / GBM);    // (8, 128)
    gemm_mma<<<grid2, 256, SM_TOTAL>>>(Uh, Ul, Wph, Wpl, out, yv);
}

// round 17
// speedup vs baseline: 1.6365x; 1.0612x over previous
#include <cuda_runtime.h>
#include <cuda_bf16.h>
#include <cstdint>

// Problem dims (fixed)
#define B_   8
#define L_   2048
#define E_   1024
#define M_   (B_ * L_)   // 16384
#define RAD  5
#define KP_  768         // packed width (heads 3,4 'first'/'last' removed)

// ---------------------------------------------------------------------------
// Scratch (__device__ globals; allocation-free rule)
// ---------------------------------------------------------------------------
__device__ float g_Wit[(size_t)KP_ * E_];   // W_in rows packed, tf32-rounded [768,1024]
__device__ float g_Wot[(size_t)E_ * KP_];   // W_out cols packed, tf32-rounded [1024,768]
__device__ float g_Vf [(size_t)M_ * KP_];   // packed V [M,768]
__device__ float g_Uf [(size_t)M_ * KP_];   // packed U [M,768] fp32
__device__ float g_xbar[16 * E_];           // weighted x rows (b,h)
__device__ float g_ubar[B_ * 256];          // per-batch const-head values
__device__ float g_yv[B_ * E_];             // per-batch broadcast output

__device__ __forceinline__ uint32_t smem_u32(const void* p) {
    uint32_t a;
    asm("{ .reg .u64 t; cvta.to.shared.u64 t, %1; cvt.u32.u64 %0, t; }" : "=r"(a) : "l"(p));
    return a;
}

#define CP_ASYNC16(dst, src) \
    asm volatile("cp.async.cg.shared.global [%0], [%1], 16;" :: "r"(dst), "l"(src))
#define CP_COMMIT() asm volatile("cp.async.commit_group;")
#define CP_WAIT(n)  asm volatile("cp.async.wait_group %0;" :: "n"(n))

#define MMA1688_TF32(acc, a0, a1, a2, a3, b0, b1)                            \
    asm volatile("mma.sync.aligned.m16n8k8.row.col.f32.tf32.tf32.f32 "       \
                 "{%0,%1,%2,%3}, {%4,%5,%6,%7}, {%8,%9}, {%0,%1,%2,%3};"     \
                 : "+f"((acc)[0]), "+f"((acc)[1]), "+f"((acc)[2]), "+f"((acc)[3]) \
                 : "r"(a0), "r"(a1), "r"(a2), "r"(a3), "r"(b0), "r"(b1))

#define LDS32(r, addr) \
    asm volatile("ld.shared.b32 %0, [%1];" : "=r"(r) : "r"(addr))
#define CVT_TF32(r) \
    asm volatile("cvt.rna.tf32.f32 %0, %0;" : "+r"(r))

// ===========================================================================
// tf32 GEMM: C[M, NOUT] = A[M,KD] @ Bt[*,KD]^T (+ optional per-batch yv)
// BM=BN=128, BK=32 (fp32 tiles, 16KB each), 256 thr, warp tile 32x64,
// 3-stage cp.async (32KB/stage), 2 CTAs/SM.
// smem: rows of 128B (32 fp32), swizzle: seg*16 ^ (row&7)*16.
// A raw fp32, cvt.rna in-register; Bt pre-rounded to tf32.
// ===========================================================================
#define G_TA 0
#define G_TB 16384
#define G_STG 32768
#define G_SMEM (3 * G_STG)   // 98304

template <int KD, int NOUT, bool ADDY>
__global__ __launch_bounds__(256, 2) void gemm_tf32(
    const float* __restrict__ A, const float* __restrict__ Bt,
    float* __restrict__ C, const float* __restrict__ yv)
{
    constexpr int NCHUNK = KD / 32;
    extern __shared__ char smem[];
    const uint32_t smem_base = smem_u32(smem);

    const int tid  = threadIdx.x;
    const int wid  = tid >> 5;
    const int lane = tid & 31;
    const int wm   = wid & 3;    // M offset wm*32
    const int wn   = wid >> 2;   // N offset wn*64

    const size_t mrow0 = (size_t)blockIdx.y * 128;
    const size_t nrow0 = (size_t)blockIdx.x * 128;

    // cp.async mapping: u = tid + rep*256 (0..1023): row=u>>3, seg=u&7
    uint32_t so[4];
    const float *gA[4], *gB[4];
#pragma unroll
    for (int rep = 0; rep < 4; rep++) {
        const int u = tid + rep * 256;
        const int row = u >> 3, seg = u & 7;
        so[rep] = (uint32_t)row * 128 + (uint32_t)((seg * 16) ^ ((row & 7) * 16));
        gA[rep] = A  + (mrow0 + row) * KD + seg * 4;
        gB[rep] = Bt + (nrow0 + row) * KD + seg * 4;
    }

    // fragment lane addressing
    const int lr = lane >> 2;          // 0..7
    const int lc = lane & 3;           // 0..3
    const uint32_t rswz = (uint32_t)lr * 16;
    uint32_t aBase[2];
#pragma unroll
    for (int mt = 0; mt < 2; mt++)
        aBase[mt] = (uint32_t)(wm * 32 + mt * 16 + lr) * 128 + lc * 4;
    uint32_t bBase[8];
#pragma unroll
    for (int g = 0; g < 8; g++)
        bBase[g] = (uint32_t)(wn * 64 + g * 8 + lr) * 128 + lc * 4;

    float acc[2][8][4];
#pragma unroll
    for (int mt = 0; mt < 2; mt++)
#pragma unroll
        for (int nt = 0; nt < 8; nt++)
#pragma unroll
            for (int r = 0; r < 4; r++) acc[mt][nt][r] = 0.0f;

    auto load_chunk = [&](int ch, int stg) {
        const uint32_t sb = smem_base + (uint32_t)stg * G_STG;
        const int kb = ch * 32;
#pragma unroll
        for (int rep = 0; rep < 4; rep++) {
            CP_ASYNC16(sb + G_TA + so[rep], gA[rep] + kb);
            CP_ASYNC16(sb + G_TB + so[rep], gB[rep] + kb);
        }
        CP_COMMIT();
    };

    load_chunk(0, 0);
    load_chunk(1, 1);

#pragma unroll 1
    for (int ch = 0; ch < NCHUNK; ch++) {
        if (ch + 1 < NCHUNK) { CP_WAIT(1); } else { CP_WAIT(0); }
        __syncthreads();
        if (ch + 2 < NCHUNK) load_chunk(ch + 2, (ch + 2) % 3);

        const uint32_t sb = smem_base + (uint32_t)(ch % 3) * G_STG;
#pragma unroll
        for (int ks = 0; ks < 4; ks++) {
            const uint32_t k0 = (uint32_t)(ks * 32) ^ rswz;
            const uint32_t k1 = (uint32_t)(ks * 32 + 16) ^ rswz;
            uint32_t a[2][4];
#pragma unroll
            for (int mt = 0; mt < 2; mt++) {
                const uint32_t b0a = sb + G_TA + aBase[mt];
                LDS32(a[mt][0], b0a + k0);
                LDS32(a[mt][1], b0a + k0 + 1024);
                LDS32(a[mt][2], b0a + k1);
                LDS32(a[mt][3], b0a + k1 + 1024);
                CVT_TF32(a[mt][0]); CVT_TF32(a[mt][1]);
                CVT_TF32(a[mt][2]); CVT_TF32(a[mt][3]);
            }
#pragma unroll
            for (int g = 0; g < 8; g++) {
                uint32_t b0, b1;
                const uint32_t bb = sb + G_TB + bBase[g];
                LDS32(b0, bb + k0);
                LDS32(b1, bb + k1);
                MMA1688_TF32(acc[0][g], a[0][0], a[0][1], a[0][2], a[0][3], b0, b1);
                MMA1688_TF32(acc[1][g], a[1][0], a[1][1], a[1][2], a[1][3], b0, b1);
            }
        }
    }

    // Epilogue
    const int qr = lane >> 2;
    const int qc = (lane & 3) * 2;
#pragma unroll
    for (int mt = 0; mt < 2; mt++) {
        const size_t r0e = mrow0 + wm * 32 + mt * 16 + qr;
        const int bb = (int)(r0e >> 11);
#pragma unroll
        for (int nt = 0; nt < 8; nt++) {
            const size_t col = nrow0 + wn * 64 + nt * 8 + qc;
            float a0 = acc[mt][nt][0], a1 = acc[mt][nt][1];
            float a2 = acc[mt][nt][2], a3 = acc[mt][nt][3];
            if (ADDY) {
                const float y0 = __ldg(yv + (size_t)bb * E_ + col);
                const float y1 = __ldg(yv + (size_t)bb * E_ + col + 1);
                a0 += y0; a1 += y1; a2 += y0; a3 += y1;
            }
            *(float2*)(C + r0e * NOUT + col)       = make_float2(a0, a1);
            *(float2*)(C + (r0e + 8) * NOUT + col) = make_float2(a2, a3);
        }
    }
}

// ---------------------------------------------------------------------------
// W_in row-packed tf32 rounding: rows {0:384, 640:1024} -> [768,1024]
// ---------------------------------------------------------------------------
__global__ __launch_bounds__(256) void round_pack_rows_tf32(
    const float* __restrict__ in, float* __restrict__ outp)
{
    int idx = blockIdx.x * 256 + threadIdx.x;
    if (idx >= KP_ * E_ / 4) return;
    const int pos = idx * 4;
    const int np  = pos / E_;
    const int k   = pos % E_;
    const int n   = np < 384 ? np : np + 256;
    float4 v = *(const float4*)(in + (size_t)n * E_ + k);
    uint32_t u0 = __float_as_uint(v.x), u1 = __float_as_uint(v.y);
    uint32_t u2 = __float_as_uint(v.z), u3 = __float_as_uint(v.w);
    CVT_TF32(u0); CVT_TF32(u1); CVT_TF32(u2); CVT_TF32(u3);
    float4 o;
    o.x = __uint_as_float(u0); o.y = __uint_as_float(u1);
    o.z = __uint_as_float(u2); o.w = __uint_as_float(u3);
    ((float4*)outp)[idx] = o;
}

// ---------------------------------------------------------------------------
// W_out col-packed tf32 rounding: cols {0:384, 640:1024} -> [1024,768]
// ---------------------------------------------------------------------------
__global__ __launch_bounds__(256) void round_pack_cols_tf32(
    const float* __restrict__ in, float* __restrict__ outp)
{
    int idx = blockIdx.x * 256 + threadIdx.x;
    if (idx >= E_ * KP_ / 4) return;
    const int pos = idx * 4;
    const int n   = pos / KP_;
    const int kp  = pos % KP_;
    const int k   = kp < 384 ? kp : kp + 256;
    float4 v = *(const float4*)(in + (size_t)n * E_ + k);
    uint32_t u0 = __float_as_uint(v.x), u1 = __float_as_uint(v.y);
    uint32_t u2 = __float_as_uint(v.z), u3 = __float_as_uint(v.w);
    CVT_TF32(u0); CVT_TF32(u1); CVT_TF32(u2); CVT_TF32(u3);
    float4 o;
    o.x = __uint_as_float(u0); o.y = __uint_as_float(u1);
    o.z = __uint_as_float(u2); o.w = __uint_as_float(u3);
    ((float4*)outp)[idx] = o;
}

__device__ __constant__ float c_wt[RAD + 1] = {
    1.0f, 0.60653066f, 0.13533528f, 0.011108997f, 3.3546263e-4f, 3.7266532e-6f};

// ---------------------------------------------------------------------------
// Gaussian smoothing on packed V [M,768] -> packed fp32 U [M,768].
// ---------------------------------------------------------------------------
__global__ __launch_bounds__(192) void smooth_pack(
    const float* __restrict__ V, float* __restrict__ U)
{
    const int n = blockIdx.x;
    const int b = n >> 11;
    const int q = n & (L_ - 1);
    const int kp = threadIdx.x * 4;
    const int hp = kp >> 7;

    int c;
    switch (hp % 3) {
        case 0:  c = q;     break;
        case 1:  c = q - 1; break;
        default: c = q + 1; break;
    }

    float ax = 0.f, ay = 0.f, az = 0.f, aw = 0.f, wsum = 0.f;
#pragma unroll
    for (int d = -RAD; d <= RAD; d++) {
        const int j = c + d;
        if (j >= 0 && j < L_) {
            const float w = c_wt[d < 0 ? -d : d];
            wsum += w;
            const float4 v = *(const float4*)(V + ((size_t)b * L_ + j) * KP_ + kp);
            ax = fmaf(w, v.x, ax); ay = fmaf(w, v.y, ay);
            az = fmaf(w, v.z, az); aw = fmaf(w, v.w, aw);
        }
    }
    const float inv = 1.0f / wsum;
    float4 o;
    o.x = ax * inv; o.y = ay * inv; o.z = az * inv; o.w = aw * inv;
    *(float4*)(U + (size_t)n * KP_ + kp) = o;
}

// ---------------------------------------------------------------------------
// xbar / ubar / yvec: exact fp32 const-head path (coalesced warp dots)
// ---------------------------------------------------------------------------
__global__ __launch_bounds__(256) void xbar_kernel(
    const float* __restrict__ x, float* __restrict__ xbar)
{
    const int b = blockIdx.x >> 1;
    const int h = blockIdx.x & 1;
    float wsum = 0.f;
#pragma unroll
    for (int d = 0; d <= RAD; d++) wsum += c_wt[d];
    const float inv = 1.0f / wsum;
    for (int k = threadIdx.x; k < E_; k += 256) {
        float acc = 0.f;
#pragma unroll
        for (int d = 0; d <= RAD; d++) {
            const int j = h ? (L_ - 1 - d) : d;
            acc = fmaf(c_wt[d], x[((size_t)b * L_ + j) * E_ + k], acc);
        }
        xbar[(size_t)blockIdx.x * E_ + k] = acc * inv;
    }
}

__global__ __launch_bounds__(256) void ubar_kernel(
    const float* __restrict__ xbar, const float* __restrict__ W_in,
    float* __restrict__ ubar)
{
    const int idx  = blockIdx.x * 8 + (threadIdx.x >> 5);
    const int lane = threadIdx.x & 31;
    const int b = idx >> 8;
    const int p = idx & 255;
    const float* xb = xbar + (size_t)(b * 2 + (p >= 128 ? 1 : 0)) * E_;
    const float* wr = W_in + (size_t)(384 + p) * E_;
    float acc = 0.f;
#pragma unroll 8
    for (int k = lane; k < E_; k += 32) acc = fmaf(xb[k], wr[k], acc);
#pragma unroll
    for (int o = 16; o > 0; o >>= 1) acc += __shfl_xor_sync(0xFFFFFFFFu, acc, o);
    if (lane == 0) ubar[b * 256 + p] = acc;
}

__global__ __launch_bounds__(256) void yvec_kernel(
    const float* __restrict__ ubar, const float* __restrict__ Wout,
    float* __restrict__ yv)
{
    const int idx  = blockIdx.x * 8 + (threadIdx.x >> 5);
    const int lane = threadIdx.x & 31;
    const int b = idx >> 10;
    const int n = idx & 1023;
    const float* ub = ubar + b * 256;
    const float* wr = Wout + (size_t)n * E_ + 384;
    float acc = 0.f;
#pragma unroll
    for (int i = 0; i < 8; i++) {
        const int p = lane + i * 32;
        acc = fmaf(ub[p], wr[p], acc);
    }
#pragma unroll
    for (int o = 16; o > 0; o >>= 1) acc += __shfl_xor_sync(0xFFFFFFFFu, acc, o);
    if (lane == 0) yv[b * E_ + n] = acc;
}

// ---------------------------------------------------------------------------
extern "C" void kernel_launch(void* const* d_in, const int* in_sizes, int n_in,
                              void* d_out, int out_size)
{
    (void)in_sizes; (void)n_in; (void)out_size;
    const float* x     = (const float*)d_in[0];
    const float* W_in  = (const float*)d_in[1];
    const float* W_out = (const float*)d_in[2];
    float* out = (float*)d_out;

    float *Wit, *Wot, *Vf, *Uf, *xbar, *ubar, *yv;
    cudaGetSymbolAddress((void**)&Wit, g_Wit);
    cudaGetSymbolAddress((void**)&Wot, g_Wot);
    cudaGetSymbolAddress((void**)&Vf, g_Vf);
    cudaGetSymbolAddress((void**)&Uf, g_Uf);
    cudaGetSymbolAddress((void**)&xbar, g_xbar);
    cudaGetSymbolAddress((void**)&ubar, g_ubar);
    cudaGetSymbolAddress((void**)&yv, g_yv);

    cudaFuncSetAttribute((const void*)gemm_tf32<E_, KP_, false>,
                         cudaFuncAttributeMaxDynamicSharedMemorySize, G_SMEM);
    cudaFuncSetAttribute((const void*)gemm_tf32<KP_, E_, true>,
                         cudaFuncAttributeMaxDynamicSharedMemorySize, G_SMEM);

    // Weight prep (tf32-rounded packed copies)
    round_pack_rows_tf32<<<(KP_ * E_ / 4 + 255) / 256, 256>>>(W_in, Wit);
    round_pack_cols_tf32<<<(E_ * KP_ / 4 + 255) / 256, 256>>>(W_out, Wot);

    // const-head path (exact fp32)
    xbar_kernel<<<16, 256>>>(x, xbar);
    ubar_kernel<<<256, 256>>>(xbar, W_in, ubar);
    yvec_kernel<<<1024, 256>>>(ubar, W_out, yv);

    // Vp = X @ W_in_packed^T  (tf32, fp32 out [M,768])
    dim3 grid1(KP_ / 128, M_ / 128);   // (6, 128)
    gemm_tf32<E_, KP_, false><<<grid1, 256, G_SMEM>>>(x, Wit, Vf, nullptr);

    // U (packed fp32) = gaussian smooth of Vp
    smooth_pack<<<M_, 192>>>(Vf, Uf);

    // out = U @ W_out_packed^T + broadcast(yv)  (tf32)
    dim3 grid2(E_ / 128, M_ / 128);    // (8, 128)
    gemm_tf32<KP_, E_, true><<<grid2, 256, G_SMEM>>>(Uf, Wot, out, yv);
}